// round 11
// baseline (speedup 1.0000x reference)
#include <cuda_runtime.h>
#include <cuda_fp16.h>
#include <cstdint>
#include <math.h>

#define NROWS 4096
#define DIM   1024
#define TEMP_INV 20.0f
#define EPS 1e-8f

#define BM 128
#define BN 128
#define BK 64
#define NKT (DIM / BK)        // 16 k-tiles
#define ROWB 128              // smem row stride in bytes (XOR swizzle, 8 chunks)
#define MAT_BYTES (128 * ROWB)        // 16384 per matrix per stage
#define OFF_A 0
#define OFF_B MAT_BYTES
#define STAGE  (2 * MAT_BYTES)        // 32768
#define NSTG   3
#define SMEM_TOTAL (NSTG * STAGE)     // 98304 -> 2 CTAs/SM

// swizzled byte offset: row r (0..127), 16B chunk c (0..7); conflict-free for
// 8-row ldmatrix phases and the cp.async write pattern
#define SWZ_OFF(r, c) ((r) * ROWB + ((((c) ^ ((r) & 7))) << 4))

// fp16 normalized inputs (allocation-free scratch)
__device__ __half g_xh[NROWS * DIM];
__device__ __half g_yh[NROWS * DIM];

// ---------------------------------------------------------------------------
// helpers
// ---------------------------------------------------------------------------
__device__ __forceinline__ uint32_t smem_to_u32(const void* p) {
    uint32_t a;
    asm("{ .reg .u64 t; cvta.to.shared.u64 t, %1; cvt.u32.u64 %0, t; }"
        : "=r"(a) : "l"(p));
    return a;
}

__device__ __forceinline__ void cp_async16(uint32_t s, const void* g) {
    asm volatile("cp.async.cg.shared.global [%0], [%1], 16;" :: "r"(s), "l"(g));
}

__device__ __forceinline__ void ldsm_x4(uint32_t& r0, uint32_t& r1,
                                        uint32_t& r2, uint32_t& r3, uint32_t addr) {
    asm volatile("ldmatrix.sync.aligned.m8n8.x4.shared.b16 {%0,%1,%2,%3}, [%4];"
                 : "=r"(r0), "=r"(r1), "=r"(r2), "=r"(r3) : "r"(addr));
}

__device__ __forceinline__ void mma16816(float* d, const uint32_t* a,
                                         uint32_t b0, uint32_t b1) {
    asm volatile(
        "mma.sync.aligned.m16n8k16.row.col.f32.f16.f16.f32 "
        "{%0,%1,%2,%3}, {%4,%5,%6,%7}, {%8,%9}, {%0,%1,%2,%3};"
        : "+f"(d[0]), "+f"(d[1]), "+f"(d[2]), "+f"(d[3])
        : "r"(a[0]), "r"(a[1]), "r"(a[2]), "r"(a[3]), "r"(b0), "r"(b1));
}

// ---------------------------------------------------------------------------
// Kernel 1: normalize rows, emit fp16. One warp per row, no block sync.
// ---------------------------------------------------------------------------
__global__ __launch_bounds__(256) void normalize_kernel(
    const float* __restrict__ x, const float* __restrict__ y) {
    const int lane = threadIdx.x & 31;
    const int row = blockIdx.x * 8 + (threadIdx.x >> 5);

    const float* src;
    __half* dst;
    if (row < NROWS) {
        src = x + (size_t)row * DIM;
        dst = g_xh + (size_t)row * DIM;
    } else {
        src = y + (size_t)(row - NROWS) * DIM;
        dst = g_yh + (size_t)(row - NROWS) * DIM;
    }

    float4 v[8];
    float s = 0.0f;
    #pragma unroll
    for (int i = 0; i < 8; i++) {
        v[i] = ((const float4*)src)[lane + i * 32];
        s += v[i].x * v[i].x + v[i].y * v[i].y + v[i].z * v[i].z + v[i].w * v[i].w;
    }
    #pragma unroll
    for (int o = 16; o; o >>= 1) s += __shfl_xor_sync(0xffffffffu, s, o);
    float inv = 1.0f / fmaxf(sqrtf(s), EPS);

    #pragma unroll
    for (int i = 0; i < 8; i++) {
        __half2 p0 = __floats2half2_rn(v[i].x * inv, v[i].y * inv);
        __half2 p1 = __floats2half2_rn(v[i].z * inv, v[i].w * inv);
        ((uint2*)dst)[lane + i * 32] = make_uint2(*(uint32_t*)&p0, *(uint32_t*)&p1);
    }
}

// ---------------------------------------------------------------------------
// One ks-block: 32 MMAs with next-fragment ldsm and cp.async chunks threaded
// between MMA quads (asm volatile order is preserved into SASS).
// LD: load next ks fragments into anx/bnx.  CP: issue 8 cp.async (one half).
// ---------------------------------------------------------------------------
template <bool LD, bool CP>
__device__ __forceinline__ void ks_block(
    float acc[4][8][4],
    const uint32_t af[4][4], const uint32_t bf[4][4],
    uint32_t anx[4][4], uint32_t bnx[4][4],
    uint32_t sA, uint32_t sB, int ch,
    int arow, int brow,
    const uint32_t* cp_so, const uint32_t* cp_go,
    uint32_t cp_sA, uint32_t cp_sB,
    const __half* gA, const __half* gB, int cp_i0)
{
    #pragma unroll
    for (int q = 0; q < 8; q++) {
        if (LD) {
            if (q < 4) {
                uint32_t ro = SWZ_OFF(arow + q * 16, ch);
                ldsm_x4(anx[q][0], anx[q][1], anx[q][2], anx[q][3], sA + ro);
            } else {
                uint32_t ro = SWZ_OFF(brow + (q - 4) * 16, ch);
                ldsm_x4(bnx[q - 4][0], bnx[q - 4][1], bnx[q - 4][2], bnx[q - 4][3], sB + ro);
            }
        }
        if (CP) {
            const int i = cp_i0 + (q >> 1);
            if ((q & 1) == 0) cp_async16(cp_sA + cp_so[i], gA + cp_go[i]);
            else              cp_async16(cp_sB + cp_so[i], gB + cp_go[i]);
        }
        const int mi = q >> 1;
        const int n0 = (q & 1) * 4;
        #pragma unroll
        for (int nt = n0; nt < n0 + 4; nt++) {
            const int nj = nt >> 1, h = nt & 1;
            mma16816(acc[mi][nt], af[mi], bf[nj][h], bf[nj][h + 2]);
        }
    }
}

// ---------------------------------------------------------------------------
// Kernel 2: fp16 HMMA GEMM. C[n][m] = 20 * (xn[n] . yn[m])
// 128x128 CTA tile, BK=64, 3-stage cp.async pipeline, 4 warps (2x2),
// warp tile 64x64, register double-buffered frags, interleaved issue,
// 2 CTAs/SM.
// ---------------------------------------------------------------------------
__global__ __launch_bounds__(128, 2) void gemm_hmma(float* __restrict__ C) {
    extern __shared__ __align__(128) char smem[];
    const int tid = threadIdx.x;
    const int lane = tid & 31;
    const int wid = tid >> 5;
    const int wm = wid >> 1;       // 0..1  (M)
    const int wn = wid & 1;        // 0..1  (N)
    const int bx = blockIdx.x;     // N tile
    const int by = blockIdx.y;     // M tile

    const uint32_t sbase = smem_to_u32(smem);

    const __half* __restrict__ A = g_xh + (size_t)(by * BM) * DIM;
    const __half* __restrict__ B = g_yh + (size_t)(bx * BN) * DIM;

    // per-thread cp.async mapping (8 chunk slots per matrix)
    uint32_t cp_so[8], cp_go[8];
    #pragma unroll
    for (int i = 0; i < 8; i++) {
        int idx = tid + i * 128;
        int row = idx >> 3;
        int ch  = idx & 7;
        cp_so[i] = SWZ_OFF(row, ch);
        cp_go[i] = (uint32_t)(row * DIM + ch * 8);
    }

    auto load_stage_burst = [&](int sidx, int kt) {
        const uint32_t sb = sbase + sidx * STAGE;
        const __half* gA = A + kt * BK;
        const __half* gB = B + kt * BK;
        #pragma unroll
        for (int i = 0; i < 8; i++) {
            cp_async16(sb + OFF_A + cp_so[i], gA + cp_go[i]);
            cp_async16(sb + OFF_B + cp_so[i], gB + cp_go[i]);
        }
        asm volatile("cp.async.commit_group;" ::: "memory");
    };

    float acc[4][8][4];
    #pragma unroll
    for (int i = 0; i < 4; i++)
        #pragma unroll
        for (int j = 0; j < 8; j++)
            #pragma unroll
            for (int k = 0; k < 4; k++) acc[i][j][k] = 0.0f;

    load_stage_burst(0, 0);
    load_stage_burst(1, 1);

    // ldmatrix row/chunk mapping
    const int arow = wm * 64 + (lane & 15);   // + mi*16
    const int brow = wn * 64 + (lane & 15);   // + nj*16
    const int chi  = lane >> 4;               // 0 or 1

    uint32_t a[2][4][4], b[2][4][4];

    for (int kt = 0; kt < NKT; kt++) {
        if (kt + 1 < NKT)
            asm volatile("cp.async.wait_group 1;" ::: "memory");
        else
            asm volatile("cp.async.wait_group 0;" ::: "memory");
        __syncthreads();

        const uint32_t sb = sbase + (kt % NSTG) * STAGE;
        const uint32_t sA = sb + OFF_A;
        const uint32_t sB = sb + OFF_B;
        const bool pf = (kt + 2 < NKT);
        const uint32_t pb = sbase + ((kt + 2) % NSTG) * STAGE;
        const uint32_t cp_sA = pb + OFF_A;
        const uint32_t cp_sB = pb + OFF_B;
        const __half* gA = A + (kt + 2) * BK;
        const __half* gB = B + (kt + 2) * BK;

        // ks0 fragment preamble (unavoidable serial ldsm)
        {
            const int ch = chi;
            #pragma unroll
            for (int mi = 0; mi < 4; mi++) {
                uint32_t ro = SWZ_OFF(arow + mi * 16, ch);
                ldsm_x4(a[0][mi][0], a[0][mi][1], a[0][mi][2], a[0][mi][3], sA + ro);
            }
            #pragma unroll
            for (int nj = 0; nj < 4; nj++) {
                uint32_t ro = SWZ_OFF(brow + nj * 16, ch);
                ldsm_x4(b[0][nj][0], b[0][nj][1], b[0][nj][2], b[0][nj][3], sB + ro);
            }
        }

        // ks0: compute a0/b0, load ks1 frags, cp half 0
        if (pf)
            ks_block<true, true >(acc, a[0], b[0], a[1], b[1], sA, sB, 2 + chi,
                                  arow, brow, cp_so, cp_go, cp_sA, cp_sB, gA, gB, 0);
        else
            ks_block<true, false>(acc, a[0], b[0], a[1], b[1], sA, sB, 2 + chi,
                                  arow, brow, cp_so, cp_go, cp_sA, cp_sB, gA, gB, 0);

        // ks1: compute a1/b1, load ks2 frags, cp half 1
        if (pf)
            ks_block<true, true >(acc, a[1], b[1], a[0], b[0], sA, sB, 4 + chi,
                                  arow, brow, cp_so, cp_go, cp_sA, cp_sB, gA, gB, 4);
        else
            ks_block<true, false>(acc, a[1], b[1], a[0], b[0], sA, sB, 4 + chi,
                                  arow, brow, cp_so, cp_go, cp_sA, cp_sB, gA, gB, 4);
        asm volatile("cp.async.commit_group;" ::: "memory");

        // ks2: compute a0/b0, load ks3 frags
        ks_block<true, false>(acc, a[0], b[0], a[1], b[1], sA, sB, 6 + chi,
                              arow, brow, cp_so, cp_go, cp_sA, cp_sB, gA, gB, 0);

        // ks3: compute a1/b1
        ks_block<false, false>(acc, a[1], b[1], a[0], b[0], sA, sB, 0,
                               arow, brow, cp_so, cp_go, cp_sA, cp_sB, gA, gB, 0);
    }

    // epilogue: scale by 20, direct float2 stores
    const int erow = by * BM + wm * 64 + (lane >> 2);
    const int ecol = bx * BN + wn * 64 + (lane & 3) * 2;
    #pragma unroll
    for (int mi = 0; mi < 4; mi++) {
        #pragma unroll
        for (int nt = 0; nt < 8; nt++) {
            float* p0 = C + (size_t)(erow + mi * 16) * NROWS + ecol + nt * 8;
            float* p1 = p0 + 8 * NROWS;
            *(float2*)p0 = make_float2(acc[mi][nt][0] * TEMP_INV,
                                       acc[mi][nt][1] * TEMP_INV);
            *(float2*)p1 = make_float2(acc[mi][nt][2] * TEMP_INV,
                                       acc[mi][nt][3] * TEMP_INV);
        }
    }
}

extern "C" void kernel_launch(void* const* d_in, const int* in_sizes, int n_in,
                              void* d_out, int out_size) {
    const float* x = (const float*)d_in[0];
    const float* y = (const float*)d_in[1];
    float* out = (float*)d_out;

    normalize_kernel<<<2 * NROWS / 8, 256>>>(x, y);

    cudaFuncSetAttribute(gemm_hmma,
                         cudaFuncAttributeMaxDynamicSharedMemorySize, SMEM_TOTAL);
    dim3 grid(NROWS / BN, NROWS / BM);
    gemm_hmma<<<grid, 128, SMEM_TOTAL>>>(out);
}

// round 12
// speedup vs baseline: 1.0557x; 1.0557x over previous
#include <cuda_runtime.h>
#include <cuda_fp16.h>
#include <cstdint>
#include <math.h>

#define NROWS 4096
#define DIM   1024
#define TEMP_INV 20.0f
#define EPS 1e-8f

#define BM 128
#define BN 128
#define BK 64
#define NKT (DIM / BK)        // 16 k-tiles
#define ROWB 128              // smem row stride in bytes (XOR swizzle, 8 chunks)
#define MAT_BYTES (128 * ROWB)        // 16384 per matrix per stage
#define OFF_A 0
#define OFF_B MAT_BYTES
#define STAGE  (2 * MAT_BYTES)        // 32768
#define NSTG   3
#define SMEM_TOTAL (NSTG * STAGE)     // 98304 -> 2 CTAs/SM

// swizzled byte offset: row r (0..127), 16B chunk c (0..7); conflict-free for
// 8-row ldmatrix phases and the cp.async write pattern
#define SWZ_OFF(r, c) ((r) * ROWB + ((((c) ^ ((r) & 7))) << 4))

// fp16 normalized inputs (allocation-free scratch)
__device__ __half g_xh[NROWS * DIM];
__device__ __half g_yh[NROWS * DIM];

// ---------------------------------------------------------------------------
// helpers
// ---------------------------------------------------------------------------
__device__ __forceinline__ uint32_t smem_to_u32(const void* p) {
    uint32_t a;
    asm("{ .reg .u64 t; cvta.to.shared.u64 t, %1; cvt.u32.u64 %0, t; }"
        : "=r"(a) : "l"(p));
    return a;
}

__device__ __forceinline__ void cp_async16(uint32_t s, const void* g) {
    asm volatile("cp.async.cg.shared.global [%0], [%1], 16;" :: "r"(s), "l"(g));
}

__device__ __forceinline__ void ldsm_x4(uint32_t& r0, uint32_t& r1,
                                        uint32_t& r2, uint32_t& r3, uint32_t addr) {
    asm volatile("ldmatrix.sync.aligned.m8n8.x4.shared.b16 {%0,%1,%2,%3}, [%4];"
                 : "=r"(r0), "=r"(r1), "=r"(r2), "=r"(r3) : "r"(addr));
}

__device__ __forceinline__ void mma16816(float* d, const uint32_t* a,
                                         uint32_t b0, uint32_t b1) {
    asm volatile(
        "mma.sync.aligned.m16n8k16.row.col.f32.f16.f16.f32 "
        "{%0,%1,%2,%3}, {%4,%5,%6,%7}, {%8,%9}, {%0,%1,%2,%3};"
        : "+f"(d[0]), "+f"(d[1]), "+f"(d[2]), "+f"(d[3])
        : "r"(a[0]), "r"(a[1]), "r"(a[2]), "r"(a[3]), "r"(b0), "r"(b1));
}

// ---------------------------------------------------------------------------
// Kernel 1: normalize rows, emit fp16. One warp per row, no block sync.
// ---------------------------------------------------------------------------
__global__ __launch_bounds__(256) void normalize_kernel(
    const float* __restrict__ x, const float* __restrict__ y) {
    const int lane = threadIdx.x & 31;
    const int row = blockIdx.x * 8 + (threadIdx.x >> 5);

    const float* src;
    __half* dst;
    if (row < NROWS) {
        src = x + (size_t)row * DIM;
        dst = g_xh + (size_t)row * DIM;
    } else {
        src = y + (size_t)(row - NROWS) * DIM;
        dst = g_yh + (size_t)(row - NROWS) * DIM;
    }

    float4 v[8];
    float s = 0.0f;
    #pragma unroll
    for (int i = 0; i < 8; i++) {
        v[i] = ((const float4*)src)[lane + i * 32];
        s += v[i].x * v[i].x + v[i].y * v[i].y + v[i].z * v[i].z + v[i].w * v[i].w;
    }
    #pragma unroll
    for (int o = 16; o; o >>= 1) s += __shfl_xor_sync(0xffffffffu, s, o);
    float inv = 1.0f / fmaxf(sqrtf(s), EPS);

    #pragma unroll
    for (int i = 0; i < 8; i++) {
        __half2 p0 = __floats2half2_rn(v[i].x * inv, v[i].y * inv);
        __half2 p1 = __floats2half2_rn(v[i].z * inv, v[i].w * inv);
        ((uint2*)dst)[lane + i * 32] = make_uint2(*(uint32_t*)&p0, *(uint32_t*)&p1);
    }
}

// ---------------------------------------------------------------------------
// Kernel 2: fp16 HMMA GEMM. C[n][m] = 20 * (xn[n] . yn[m])
// 128x128 CTA tile, BK=64, 3-stage cp.async pipeline with split-issue loads,
// 4 warps (2x2), warp tile 64x64, register double-buffered frags, 2 CTAs/SM.
// NEW: co-resident-CTA phase stagger (bids 148.. delayed ~1300 cyc) so the
// two CTAs sharing each SMSP anti-align their barrier/ldsm stalls.
// ---------------------------------------------------------------------------
__global__ __launch_bounds__(128, 2) void gemm_hmma(float* __restrict__ C) {
    extern __shared__ __align__(128) char smem[];
    const int tid = threadIdx.x;
    const int lane = tid & 31;
    const int wid = tid >> 5;
    const int wm = wid >> 1;       // 0..1  (M)
    const int wn = wid & 1;        // 0..1  (N)
    const int bx = blockIdx.x;     // N tile
    const int by = blockIdx.y;     // M tile

    // --- phase stagger: wave-2 co-residents get a one-time ~1300cyc delay ---
    {
        const int bid = by * gridDim.x + bx;
        if ((bid / 148) & 1) {
            float t = 1.0f;
            #pragma unroll 16
            for (int i = 0; i < 320; i++)
                asm volatile("fma.rn.f32 %0, %0, %1, %2;"
                             : "+f"(t) : "f"(1.0000001f), "f"(1e-30f));
            // consume t so it can never be stripped
            if (t == 2.0f) smem[0] = 0;
        }
    }

    const uint32_t sbase = smem_to_u32(smem);

    const __half* __restrict__ A = g_xh + (size_t)(by * BM) * DIM;
    const __half* __restrict__ B = g_yh + (size_t)(bx * BN) * DIM;

    // loader halves: 128 rows x 8 chunks per matrix; 8/thread/matrix total,
    // issued as two halves of 4+4 to spread LSU dispatch pressure.
    auto load_half = [&](int sidx, int kt, int half) {
        const uint32_t sb = sbase + sidx * STAGE;
        const int k0 = kt * BK;
        #pragma unroll
        for (int i = half * 4; i < half * 4 + 4; i++) {
            int idx = tid + i * 128;
            int row = idx >> 3;
            int ch  = idx & 7;
            uint32_t so = SWZ_OFF(row, ch);
            size_t go = (size_t)row * DIM + k0 + ch * 8;
            cp_async16(sb + OFF_A + so, A + go);
            cp_async16(sb + OFF_B + so, B + go);
        }
    };
    auto commit = [] {
        asm volatile("cp.async.commit_group;" ::: "memory");
    };

    float acc[4][8][4];
    #pragma unroll
    for (int i = 0; i < 4; i++)
        #pragma unroll
        for (int j = 0; j < 8; j++)
            #pragma unroll
            for (int k = 0; k < 4; k++) acc[i][j][k] = 0.0f;

    load_half(0, 0, 0); load_half(0, 0, 1); commit();
    load_half(1, 1, 0); load_half(1, 1, 1); commit();

    // ldmatrix row/chunk mapping
    const int arow = wm * 64 + (lane & 15);   // + mi*16
    const int brow = wn * 64 + (lane & 15);   // + nj*16
    const int chi  = lane >> 4;               // 0 or 1

    uint32_t a[2][4][4], b[2][4][4];

    for (int kt = 0; kt < NKT; kt++) {
        if (kt + 1 < NKT)
            asm volatile("cp.async.wait_group 1;" ::: "memory");
        else
            asm volatile("cp.async.wait_group 0;" ::: "memory");
        __syncthreads();

        const uint32_t sb = sbase + (kt % NSTG) * STAGE;
        const uint32_t sA = sb + OFF_A;
        const uint32_t sB = sb + OFF_B;
        const bool pf = (kt + 2 < NKT);
        const int pidx = (kt + 2) % NSTG;

        auto ld_frags = [&](int ks, uint32_t af[4][4], uint32_t bf[4][4]) {
            const int ch = ks * 2 + chi;
            #pragma unroll
            for (int mi = 0; mi < 4; mi++) {
                uint32_t ro = SWZ_OFF(arow + mi * 16, ch);
                ldsm_x4(af[mi][0], af[mi][1], af[mi][2], af[mi][3], sA + ro);
            }
            #pragma unroll
            for (int nj = 0; nj < 4; nj++) {
                uint32_t ro = SWZ_OFF(brow + nj * 16, ch);
                ldsm_x4(bf[nj][0], bf[nj][1], bf[nj][2], bf[nj][3], sB + ro);
            }
        };
        auto mma_block = [&](uint32_t af[4][4], uint32_t bf[4][4]) {
            #pragma unroll
            for (int mi = 0; mi < 4; mi++) {
                #pragma unroll
                for (int nt = 0; nt < 8; nt++) {
                    const int nj = nt >> 1, h = nt & 1;
                    mma16816(acc[mi][nt], af[mi], bf[nj][h], bf[nj][h + 2]);
                }
            }
        };

        ld_frags(0, a[0], b[0]);

        // ks = 0
        ld_frags(1, a[1], b[1]);
        mma_block(a[0], b[0]);
        if (pf) load_half(pidx, kt + 2, 0);     // spread LSU pressure

        // ks = 1
        ld_frags(2, a[0], b[0]);
        mma_block(a[1], b[1]);
        if (pf) { load_half(pidx, kt + 2, 1); }
        commit();                                // one group per stage (empty if !pf)

        // ks = 2
        ld_frags(3, a[1], b[1]);
        mma_block(a[0], b[0]);

        // ks = 3
        mma_block(a[1], b[1]);
    }

    // epilogue: scale by 20, direct float2 stores
    const int erow = by * BM + wm * 64 + (lane >> 2);
    const int ecol = bx * BN + wn * 64 + (lane & 3) * 2;
    #pragma unroll
    for (int mi = 0; mi < 4; mi++) {
        #pragma unroll
        for (int nt = 0; nt < 8; nt++) {
            float* p0 = C + (size_t)(erow + mi * 16) * NROWS + ecol + nt * 8;
            float* p1 = p0 + 8 * NROWS;
            *(float2*)p0 = make_float2(acc[mi][nt][0] * TEMP_INV,
                                       acc[mi][nt][1] * TEMP_INV);
            *(float2*)p1 = make_float2(acc[mi][nt][2] * TEMP_INV,
                                       acc[mi][nt][3] * TEMP_INV);
        }
    }
}

extern "C" void kernel_launch(void* const* d_in, const int* in_sizes, int n_in,
                              void* d_out, int out_size) {
    const float* x = (const float*)d_in[0];
    const float* y = (const float*)d_in[1];
    float* out = (float*)d_out;

    normalize_kernel<<<2 * NROWS / 8, 256>>>(x, y);

    cudaFuncSetAttribute(gemm_hmma,
                         cudaFuncAttributeMaxDynamicSharedMemorySize, SMEM_TOTAL);
    dim3 grid(NROWS / BN, NROWS / BM);
    gemm_hmma<<<grid, 128, SMEM_TOTAL>>>(out);
}

// round 13
// speedup vs baseline: 1.1674x; 1.1057x over previous
#include <cuda_runtime.h>
#include <cuda_fp16.h>
#include <cstdint>
#include <math.h>

#define NROWS 4096
#define DIM   1024
#define TEMP_INV 20.0f
#define EPS 1e-8f

#define BM 128
#define BN 128
#define BK 64
#define NKT (DIM / BK)        // 16 k-tiles
#define ROWB 128              // smem row stride in bytes (XOR swizzle, 8 chunks)
#define MAT_BYTES (128 * ROWB)        // 16384 per matrix per stage
#define OFF_A 0
#define OFF_B MAT_BYTES
#define STAGE  (2 * MAT_BYTES)        // 32768
#define NSTG   3
#define SMEM_TOTAL (NSTG * STAGE)     // 98304 -> 2 CTAs/SM

// swizzled byte offset: row r (0..127), 16B chunk c (0..7)
#define SWZ_OFF(r, c) ((r) * ROWB + ((((c) ^ ((r) & 7))) << 4))

// fp16 normalized inputs (allocation-free scratch)
__device__ __half g_xh[NROWS * DIM];
__device__ __half g_yh[NROWS * DIM];

// ---------------------------------------------------------------------------
// helpers
// ---------------------------------------------------------------------------
__device__ __forceinline__ uint32_t smem_to_u32(const void* p) {
    uint32_t a;
    asm("{ .reg .u64 t; cvta.to.shared.u64 t, %1; cvt.u32.u64 %0, t; }"
        : "=r"(a) : "l"(p));
    return a;
}

__device__ __forceinline__ void cp_async16(uint32_t s, const void* g) {
    asm volatile("cp.async.cg.shared.global [%0], [%1], 16;" :: "r"(s), "l"(g));
}

__device__ __forceinline__ void ldsm_x4(uint32_t& r0, uint32_t& r1,
                                        uint32_t& r2, uint32_t& r3, uint32_t addr) {
    asm volatile("ldmatrix.sync.aligned.m8n8.x4.shared.b16 {%0,%1,%2,%3}, [%4];"
                 : "=r"(r0), "=r"(r1), "=r"(r2), "=r"(r3) : "r"(addr));
}

__device__ __forceinline__ void mma16816(float* d, const uint32_t* a,
                                         uint32_t b0, uint32_t b1) {
    asm volatile(
        "mma.sync.aligned.m16n8k16.row.col.f32.f16.f16.f32 "
        "{%0,%1,%2,%3}, {%4,%5,%6,%7}, {%8,%9}, {%0,%1,%2,%3};"
        : "+f"(d[0]), "+f"(d[1]), "+f"(d[2]), "+f"(d[3])
        : "r"(a[0]), "r"(a[1]), "r"(a[2]), "r"(a[3]), "r"(b0), "r"(b1));
}

// ---------------------------------------------------------------------------
// Kernel 1: normalize rows, emit fp16. One warp per row, no block sync.
// ---------------------------------------------------------------------------
__global__ __launch_bounds__(256) void normalize_kernel(
    const float* __restrict__ x, const float* __restrict__ y) {
    const int lane = threadIdx.x & 31;
    const int row = blockIdx.x * 8 + (threadIdx.x >> 5);

    const float* src;
    __half* dst;
    if (row < NROWS) {
        src = x + (size_t)row * DIM;
        dst = g_xh + (size_t)row * DIM;
    } else {
        src = y + (size_t)(row - NROWS) * DIM;
        dst = g_yh + (size_t)(row - NROWS) * DIM;
    }

    float4 v[8];
    float s = 0.0f;
    #pragma unroll
    for (int i = 0; i < 8; i++) {
        v[i] = ((const float4*)src)[lane + i * 32];
        s += v[i].x * v[i].x + v[i].y * v[i].y + v[i].z * v[i].z + v[i].w * v[i].w;
    }
    #pragma unroll
    for (int o = 16; o; o >>= 1) s += __shfl_xor_sync(0xffffffffu, s, o);
    float inv = 1.0f / fmaxf(sqrtf(s), EPS);

    #pragma unroll
    for (int i = 0; i < 8; i++) {
        __half2 p0 = __floats2half2_rn(v[i].x * inv, v[i].y * inv);
        __half2 p1 = __floats2half2_rn(v[i].z * inv, v[i].w * inv);
        ((uint2*)dst)[lane + i * 32] = make_uint2(*(uint32_t*)&p0, *(uint32_t*)&p1);
    }
}

// ---------------------------------------------------------------------------
// Kernel 2: fp16 HMMA GEMM. C[n][m] = 20 * (xn[n] . yn[m])
// 128x128 CTA tile, BK=64, 3-stage cp.async pipeline, 4 warps (2x2),
// warp tile 64x64, register double-buffered frags, 2 CTAs/SM.
// This round: end-of-kt ks0 prefetch (no serial preamble inside kt) and
// precomputed ldsm base addresses (XOR swizzle decomposed per-thread).
// ---------------------------------------------------------------------------
__global__ __launch_bounds__(128, 2) void gemm_hmma(float* __restrict__ C) {
    extern __shared__ __align__(128) char smem[];
    const int tid = threadIdx.x;
    const int lane = tid & 31;
    const int wid = tid >> 5;
    const int wm = wid >> 1;       // 0..1  (M)
    const int wn = wid & 1;        // 0..1  (N)
    const int bx = blockIdx.x;     // N tile
    const int by = blockIdx.y;     // M tile

    const uint32_t sbase = smem_to_u32(smem);

    const __half* __restrict__ A = g_xh + (size_t)(by * BM) * DIM;
    const __half* __restrict__ B = g_yh + (size_t)(bx * BN) * DIM;

    // cp.async per-thread mapping (8 chunk slots per matrix)
    uint32_t cp_so[8], cp_go[8];
    #pragma unroll
    for (int i = 0; i < 8; i++) {
        int idx = tid + i * 128;
        int row = idx >> 3;
        int ch  = idx & 7;
        cp_so[i] = SWZ_OFF(row, ch);
        cp_go[i] = (uint32_t)(row * DIM + ch * 8);
    }

    auto load_half = [&](int sidx, int kt, int half) {
        const uint32_t sbA = sbase + sidx * STAGE + OFF_A;
        const uint32_t sbB = sbase + sidx * STAGE + OFF_B;
        const __half* gA = A + kt * BK;
        const __half* gB = B + kt * BK;
        #pragma unroll
        for (int i = half * 4; i < half * 4 + 4; i++) {
            cp_async16(sbA + cp_so[i], gA + cp_go[i]);
            cp_async16(sbB + cp_so[i], gB + cp_go[i]);
        }
    };
    auto commit = [] { asm volatile("cp.async.commit_group;" ::: "memory"); };

    float acc[4][8][4];
    #pragma unroll
    for (int i = 0; i < 4; i++)
        #pragma unroll
        for (int j = 0; j < 8; j++)
            #pragma unroll
            for (int k = 0; k < 4; k++) acc[i][j][k] = 0.0f;

    load_half(0, 0, 0); load_half(0, 0, 1); commit();
    load_half(1, 1, 0); load_half(1, 1, 1); commit();

    // -------- ldsm address precomputation --------
    // addr(r, c=ks*2+chi) = r*ROWB + ((chi^(r&1))<<4) + ((ks^pm)<<5),
    // pm = bits 1..2 of (lane&15) — identical for all fragments of a thread.
    const int arow = wm * 64 + (lane & 15);
    const int brow = wn * 64 + (lane & 15);
    const int chi  = lane >> 4;
    const int pm   = (lane >> 1) & 3;

    uint32_t abase[4], bbase[4], koff[4];
    #pragma unroll
    for (int mi = 0; mi < 4; mi++) {
        int r = arow + mi * 16;
        abase[mi] = (uint32_t)(r * ROWB + ((chi ^ (r & 1)) << 4)) + OFF_A;
        int rb = brow + mi * 16;
        bbase[mi] = (uint32_t)(rb * ROWB + ((chi ^ (rb & 1)) << 4)) + OFF_B;
    }
    #pragma unroll
    for (int ks = 0; ks < 4; ks++) koff[ks] = (uint32_t)((ks ^ pm) << 5);

    uint32_t a[2][4][4], b[2][4][4];

    // fragment loader: one 16-col k-slice from stage base sb
    auto ld_frags = [&](uint32_t sb, int ks, uint32_t af[4][4], uint32_t bf[4][4]) {
        const uint32_t t = sb + koff[ks];
        #pragma unroll
        for (int mi = 0; mi < 4; mi++)
            ldsm_x4(af[mi][0], af[mi][1], af[mi][2], af[mi][3], t + abase[mi]);
        #pragma unroll
        for (int nj = 0; nj < 4; nj++)
            ldsm_x4(bf[nj][0], bf[nj][1], bf[nj][2], bf[nj][3], t + bbase[nj]);
    };
    auto mma_block = [&](uint32_t af[4][4], uint32_t bf[4][4]) {
        #pragma unroll
        for (int mi = 0; mi < 4; mi++) {
            #pragma unroll
            for (int nt = 0; nt < 8; nt++) {
                const int nj = nt >> 1, h = nt & 1;
                mma16816(acc[mi][nt], af[mi], bf[nj][h], bf[nj][h + 2]);
            }
        }
    };

    // prologue: both stages resident, prefetch ks0 of kt0
    asm volatile("cp.async.wait_group 0;" ::: "memory");
    __syncthreads();
    ld_frags(sbase, 0, a[0], b[0]);

    uint32_t sb_cur = sbase;                       // stage kt%3 base

    for (int kt = 0; kt < NKT; kt++) {
        const bool pf = (kt + 2 < NKT);
        const int pidx = (kt + 2) % NSTG;

        // ks0: a[0]/b[0] already loaded (prefetched at end of previous kt)
        ld_frags(sb_cur, 1, a[1], b[1]);
        mma_block(a[0], b[0]);
        if (pf) load_half(pidx, kt + 2, 0);

        // ks1
        ld_frags(sb_cur, 2, a[0], b[0]);
        mma_block(a[1], b[1]);
        if (pf) load_half(pidx, kt + 2, 1);
        commit();                                  // one group per kt (may be empty)

        // ks2
        ld_frags(sb_cur, 3, a[1], b[1]);
        mma_block(a[0], b[0]);

        // ks3
        mma_block(a[1], b[1]);

        if (kt + 1 < NKT) {
            // ensure stage kt+1 fully resident, visible to all threads, then
            // prefetch its ks0 frags. Refill during kt+1 targets a different
            // buffer ((kt+3)%3 == kt%3), so no read/write overlap.
            asm volatile("cp.async.wait_group 1;" ::: "memory");
            __syncthreads();
            sb_cur = sbase + ((kt + 1) % NSTG) * STAGE;
            ld_frags(sb_cur, 0, a[0], b[0]);
        }
    }

    // epilogue: scale by 20, direct float2 stores
    const int erow = by * BM + wm * 64 + (lane >> 2);
    const int ecol = bx * BN + wn * 64 + (lane & 3) * 2;
    #pragma unroll
    for (int mi = 0; mi < 4; mi++) {
        #pragma unroll
        for (int nt = 0; nt < 8; nt++) {
            float* p0 = C + (size_t)(erow + mi * 16) * NROWS + ecol + nt * 8;
            float* p1 = p0 + 8 * NROWS;
            *(float2*)p0 = make_float2(acc[mi][nt][0] * TEMP_INV,
                                       acc[mi][nt][1] * TEMP_INV);
            *(float2*)p1 = make_float2(acc[mi][nt][2] * TEMP_INV,
                                       acc[mi][nt][3] * TEMP_INV);
        }
    }
}

extern "C" void kernel_launch(void* const* d_in, const int* in_sizes, int n_in,
                              void* d_out, int out_size) {
    const float* x = (const float*)d_in[0];
    const float* y = (const float*)d_in[1];
    float* out = (float*)d_out;

    normalize_kernel<<<2 * NROWS / 8, 256>>>(x, y);

    cudaFuncSetAttribute(gemm_hmma,
                         cudaFuncAttributeMaxDynamicSharedMemorySize, SMEM_TOTAL);
    dim3 grid(NROWS / BN, NROWS / BM);
    gemm_hmma<<<grid, 128, SMEM_TOTAL>>>(out);
}

// round 14
// speedup vs baseline: 1.2713x; 1.0890x over previous
#include <cuda_runtime.h>
#include <cuda_fp16.h>
#include <cstdint>
#include <math.h>

#define NROWS 4096
#define DIM   1024
#define TEMP_INV 20.0f
#define EPS 1e-8f

#define BM 128
#define BN 128
#define BK 64
#define NKT (DIM / BK)        // 16 k-tiles
#define ROWB 128              // smem row stride in bytes (XOR swizzle, 8 chunks)
#define MAT_BYTES (128 * ROWB)        // 16384 per matrix per stage
#define OFF_A 0
#define OFF_B MAT_BYTES
#define STAGE  (2 * MAT_BYTES)        // 32768
#define NSTG   3
#define SMEM_TOTAL (NSTG * STAGE)     // 98304 -> 2 CTAs/SM

// swizzled byte offset: row r (0..127), 16B chunk c (0..7)
#define SWZ_OFF(r, c) ((r) * ROWB + ((((c) ^ ((r) & 7))) << 4))

// fp16 normalized inputs (allocation-free scratch)
__device__ __half g_xh[NROWS * DIM];
__device__ __half g_yh[NROWS * DIM];

// ---------------------------------------------------------------------------
// helpers
// ---------------------------------------------------------------------------
__device__ __forceinline__ uint32_t smem_to_u32(const void* p) {
    uint32_t a;
    asm("{ .reg .u64 t; cvta.to.shared.u64 t, %1; cvt.u32.u64 %0, t; }"
        : "=r"(a) : "l"(p));
    return a;
}

__device__ __forceinline__ void cp_async16(uint32_t s, const void* g) {
    asm volatile("cp.async.cg.shared.global [%0], [%1], 16;" :: "r"(s), "l"(g));
}

__device__ __forceinline__ void ldsm_x4(uint32_t& r0, uint32_t& r1,
                                        uint32_t& r2, uint32_t& r3, uint32_t addr) {
    asm volatile("ldmatrix.sync.aligned.m8n8.x4.shared.b16 {%0,%1,%2,%3}, [%4];"
                 : "=r"(r0), "=r"(r1), "=r"(r2), "=r"(r3) : "r"(addr));
}

__device__ __forceinline__ void mma16816(float* d, const uint32_t* a,
                                         uint32_t b0, uint32_t b1) {
    asm volatile(
        "mma.sync.aligned.m16n8k16.row.col.f32.f16.f16.f32 "
        "{%0,%1,%2,%3}, {%4,%5,%6,%7}, {%8,%9}, {%0,%1,%2,%3};"
        : "+f"(d[0]), "+f"(d[1]), "+f"(d[2]), "+f"(d[3])
        : "r"(a[0]), "r"(a[1]), "r"(a[2]), "r"(a[3]), "r"(b0), "r"(b1));
}

// ---------------------------------------------------------------------------
// Kernel 1: normalize rows, emit fp16. One warp per row, no block sync.
// ---------------------------------------------------------------------------
__global__ __launch_bounds__(256) void normalize_kernel(
    const float* __restrict__ x, const float* __restrict__ y) {
    const int lane = threadIdx.x & 31;
    const int row = blockIdx.x * 8 + (threadIdx.x >> 5);

    const float* src;
    __half* dst;
    if (row < NROWS) {
        src = x + (size_t)row * DIM;
        dst = g_xh + (size_t)row * DIM;
    } else {
        src = y + (size_t)(row - NROWS) * DIM;
        dst = g_yh + (size_t)(row - NROWS) * DIM;
    }

    float4 v[8];
    float s = 0.0f;
    #pragma unroll
    for (int i = 0; i < 8; i++) {
        v[i] = ((const float4*)src)[lane + i * 32];
        s += v[i].x * v[i].x + v[i].y * v[i].y + v[i].z * v[i].z + v[i].w * v[i].w;
    }
    #pragma unroll
    for (int o = 16; o; o >>= 1) s += __shfl_xor_sync(0xffffffffu, s, o);
    float inv = 1.0f / fmaxf(sqrtf(s), EPS);

    #pragma unroll
    for (int i = 0; i < 8; i++) {
        __half2 p0 = __floats2half2_rn(v[i].x * inv, v[i].y * inv);
        __half2 p1 = __floats2half2_rn(v[i].z * inv, v[i].w * inv);
        ((uint2*)dst)[lane + i * 32] = make_uint2(*(uint32_t*)&p0, *(uint32_t*)&p1);
    }
}

// ---------------------------------------------------------------------------
// Kernel 2: fp16 HMMA GEMM. C[n][m] = 20 * (xn[n] . yn[m])
// 128x128 CTA tile, BK=64, 3-stage cp.async pipeline, 4 warps (2x2),
// warp tile 64x64, register double-buffered frags, 2 CTAs/SM.
// This round: peel + group-of-3 kt loop so stage bases are compile-time
// constants; global pointers strength-reduced to one walk per group.
// ---------------------------------------------------------------------------
__global__ __launch_bounds__(128, 2) void gemm_hmma(float* __restrict__ C) {
    extern __shared__ __align__(128) char smem[];
    const int tid = threadIdx.x;
    const int lane = tid & 31;
    const int wid = tid >> 5;
    const int wm = wid >> 1;       // 0..1  (M)
    const int wn = wid & 1;        // 0..1  (N)
    const int bx = blockIdx.x;     // N tile
    const int by = blockIdx.y;     // M tile

    const uint32_t sbase = smem_to_u32(smem);
    const uint32_t S0 = sbase, S1 = sbase + STAGE, S2 = sbase + 2 * STAGE;

    const __half* __restrict__ A = g_xh + (size_t)(by * BM) * DIM;
    const __half* __restrict__ B = g_yh + (size_t)(bx * BN) * DIM;

    // cp.async per-thread mapping (8 chunk slots per matrix)
    uint32_t cp_so[8], cp_go[8];
    #pragma unroll
    for (int i = 0; i < 8; i++) {
        int idx = tid + i * 128;
        int row = idx >> 3;
        int ch  = idx & 7;
        cp_so[i] = SWZ_OFF(row, ch);
        cp_go[i] = (uint32_t)(row * DIM + ch * 8);
    }

    // fill one half (4 chunks x 2 matrices) of buffer at smem base 'fsb'
    // from global stage pointers gA/gB
    auto load_half = [&](uint32_t fsb, const __half* gA, const __half* gB, int half) {
        #pragma unroll
        for (int i = half * 4; i < half * 4 + 4; i++) {
            cp_async16(fsb + OFF_A + cp_so[i], gA + cp_go[i]);
            cp_async16(fsb + OFF_B + cp_so[i], gB + cp_go[i]);
        }
    };
    auto commit = [] { asm volatile("cp.async.commit_group;" ::: "memory"); };

    float acc[4][8][4];
    #pragma unroll
    for (int i = 0; i < 4; i++)
        #pragma unroll
        for (int j = 0; j < 8; j++)
            #pragma unroll
            for (int k = 0; k < 4; k++) acc[i][j][k] = 0.0f;

    load_half(S0, A, B, 0);           load_half(S0, A, B, 1);           commit();
    load_half(S1, A + BK, B + BK, 0); load_half(S1, A + BK, B + BK, 1); commit();

    // -------- ldsm address precomputation --------
    // addr(r, c=ks*2+chi) = r*ROWB + ((chi^(r&1))<<4) + ((ks^pm)<<5)
    const int arow = wm * 64 + (lane & 15);
    const int brow = wn * 64 + (lane & 15);
    const int chi  = lane >> 4;
    const int pm   = (lane >> 1) & 3;

    uint32_t abase[4], bbase[4], koff[4];
    #pragma unroll
    for (int mi = 0; mi < 4; mi++) {
        int r = arow + mi * 16;
        abase[mi] = (uint32_t)(r * ROWB + ((chi ^ (r & 1)) << 4)) + OFF_A;
        int rb = brow + mi * 16;
        bbase[mi] = (uint32_t)(rb * ROWB + ((chi ^ (rb & 1)) << 4)) + OFF_B;
    }
    #pragma unroll
    for (int ks = 0; ks < 4; ks++) koff[ks] = (uint32_t)((ks ^ pm) << 5);

    uint32_t a[2][4][4], b[2][4][4];

    auto ld_frags = [&](uint32_t sb, int ks, uint32_t af[4][4], uint32_t bf[4][4]) {
        const uint32_t t = sb + koff[ks];
        #pragma unroll
        for (int mi = 0; mi < 4; mi++)
            ldsm_x4(af[mi][0], af[mi][1], af[mi][2], af[mi][3], t + abase[mi]);
        #pragma unroll
        for (int nj = 0; nj < 4; nj++)
            ldsm_x4(bf[nj][0], bf[nj][1], bf[nj][2], bf[nj][3], t + bbase[nj]);
    };
    auto mma_block = [&](uint32_t af[4][4], uint32_t bf[4][4]) {
        #pragma unroll
        for (int mi = 0; mi < 4; mi++) {
            #pragma unroll
            for (int nt = 0; nt < 8; nt++) {
                const int nj = nt >> 1, h = nt & 1;
                mma16816(acc[mi][nt], af[mi], bf[nj][h], bf[nj][h + 2]);
            }
        }
    };

    // one k-tile: consume buffer 'sb'; optionally fill 'fsb' with stage at
    // gA/gB; unless 'last', wait for next stage + barrier (caller then
    // prefetches ks0 of the next buffer).
    auto do_kt = [&](uint32_t sb, uint32_t fsb,
                     const __half* gA, const __half* gB, bool pf, bool last) {
        ld_frags(sb, 1, a[1], b[1]);
        mma_block(a[0], b[0]);
        if (pf) load_half(fsb, gA, gB, 0);

        ld_frags(sb, 2, a[0], b[0]);
        mma_block(a[1], b[1]);
        if (pf) load_half(fsb, gA, gB, 1);
        commit();                       // one group per kt (may be empty)

        ld_frags(sb, 3, a[1], b[1]);
        mma_block(a[0], b[0]);
        mma_block(a[1], b[1]);

        if (!last) {
            asm volatile("cp.async.wait_group 1;" ::: "memory");
            __syncthreads();
        }
    };

    // prologue: stage 0 resident, prefetch its ks0
    asm volatile("cp.async.wait_group 1;" ::: "memory");
    __syncthreads();
    ld_frags(S0, 0, a[0], b[0]);

    // peel kt=0 (buffer S0; fills stage 2 -> S2)
    do_kt(S0, S2, A + 2 * BK, B + 2 * BK, true, false);
    ld_frags(S1, 0, a[0], b[0]);

    const __half* pA = A + 3 * BK;   // stage kt+2 pointer for kt = 1
    const __half* pB = B + 3 * BK;

    for (int g = 0; g < 5; g++) {
        const int kt = 1 + 3 * g;
        const bool lastg = (g == 4);

        // kt (buffer S1; fills S0 with stage kt+2)
        do_kt(S1, S0, pA, pB, kt + 2 < NKT, false);
        ld_frags(S2, 0, a[0], b[0]);

        // kt+1 (buffer S2; fills S1 with stage kt+3)
        do_kt(S2, S1, pA + BK, pB + BK, kt + 3 < NKT, false);
        ld_frags(S0, 0, a[0], b[0]);

        // kt+2 (buffer S0; fills S2 with stage kt+4)
        do_kt(S0, S2, pA + 2 * BK, pB + 2 * BK, kt + 4 < NKT, lastg);
        if (!lastg) ld_frags(S1, 0, a[0], b[0]);

        pA += 3 * BK;
        pB += 3 * BK;
    }

    // epilogue: scale by 20, direct float2 stores
    const int erow = by * BM + wm * 64 + (lane >> 2);
    const int ecol = bx * BN + wn * 64 + (lane & 3) * 2;
    #pragma unroll
    for (int mi = 0; mi < 4; mi++) {
        #pragma unroll
        for (int nt = 0; nt < 8; nt++) {
            float* p0 = C + (size_t)(erow + mi * 16) * NROWS + ecol + nt * 8;
            float* p1 = p0 + 8 * NROWS;
            *(float2*)p0 = make_float2(acc[mi][nt][0] * TEMP_INV,
                                       acc[mi][nt][1] * TEMP_INV);
            *(float2*)p1 = make_float2(acc[mi][nt][2] * TEMP_INV,
                                       acc[mi][nt][3] * TEMP_INV);
        }
    }
}

extern "C" void kernel_launch(void* const* d_in, const int* in_sizes, int n_in,
                              void* d_out, int out_size) {
    const float* x = (const float*)d_in[0];
    const float* y = (const float*)d_in[1];
    float* out = (float*)d_out;

    normalize_kernel<<<2 * NROWS / 8, 256>>>(x, y);

    cudaFuncSetAttribute(gemm_hmma,
                         cudaFuncAttributeMaxDynamicSharedMemorySize, SMEM_TOTAL);
    dim3 grid(NROWS / BN, NROWS / BM);
    gemm_hmma<<<grid, 128, SMEM_TOTAL>>>(out);
}